// round 13
// baseline (speedup 1.0000x reference)
#include <cuda_runtime.h>
#include <cuda_bf16.h>
#include <cstdint>

#define NN 100000
#define NE 1600000
#define HDIM 128

// ---------------- static device scratch ----------------
__device__ uint4 g_bufAhi[(size_t)NN * 16];  // agg output, hi bf16 plane (N x K)
__device__ uint4 g_bufAlo[(size_t)NN * 16];  // agg output, lo bf16 plane
__device__ float4 g_bufB[(size_t)NN * 32];   // pre-BN linear output (fp32)
__device__ float4 g_bufC[(size_t)NN * 32];   // layer outputs (fp32)

__device__ int g_counts[NN];
__device__ int g_scanTmp[NN];
__device__ int g_partials[128];
__device__ int g_rowptr[NN + 1];
__device__ int g_cursor[NN];
__device__ int g_srcSorted[NE];
__device__ int g_is64;

__device__ float g_Ssum[HDIM];
__device__ float g_Ssq[HDIM];

// Pre-swizzled B fragments: slot s, chunk c (k/16), ntile t (n/8), lane.
// uint4 = {bh_reg0, bh_reg1, bl_reg0, bl_reg1} for mma m16n8k16 (split bf16).
__device__ uint4 g_Wfrag[7 * 4096];

__device__ __forceinline__ int edge_at(const int* __restrict__ ei, long long pos, int is64) {
    return is64 ? ei[2 * pos] : ei[(size_t)pos];
}

// ---------------- dtype detector ----------------
__global__ void k_detect(const int* __restrict__ ei) {
    __shared__ int nz;
    if (threadIdx.x == 0) nz = 0;
    __syncthreads();
    long long p = (long long)threadIdx.x * (NE / 256);
    if (ei[2 * p + 1] != 0) atomicAdd(&nz, 1);
    __syncthreads();
    if (threadIdx.x == 0) g_is64 = (nz == 0) ? 1 : 0;
}

// ---------------- CSR build ----------------
__global__ void k_zero_counts() {
    int i = blockIdx.x * blockDim.x + threadIdx.x;
    if (i < NN) g_counts[i] = 0;
}

__global__ void k_hist(const int* __restrict__ ei) {
    int e = blockIdx.x * blockDim.x + threadIdx.x;
    if (e < NE) {
        int is64 = g_is64;
        unsigned d = (unsigned)edge_at(ei, (long long)NE + e, is64);
        if (d < NN) atomicAdd(&g_counts[d], 1);
    }
}

__global__ void k_scan1() {
    __shared__ int s[1024];
    int idx = blockIdx.x * 1024 + threadIdx.x;
    int v = (idx < NN) ? g_counts[idx] : 0;
    s[threadIdx.x] = v;
    __syncthreads();
    for (int off = 1; off < 1024; off <<= 1) {
        int t = 0;
        if (threadIdx.x >= off) t = s[threadIdx.x - off];
        __syncthreads();
        s[threadIdx.x] += t;
        __syncthreads();
    }
    if (idx < NN) g_scanTmp[idx] = s[threadIdx.x];
    if (threadIdx.x == 1023) g_partials[blockIdx.x] = s[1023];
}

__global__ void k_scan2(int nblocks) {
    __shared__ int s[128];
    int t = threadIdx.x;
    int v = (t < nblocks) ? g_partials[t] : 0;
    s[t] = v;
    __syncthreads();
    for (int off = 1; off < 128; off <<= 1) {
        int tv = 0;
        if (t >= off) tv = s[t - off];
        __syncthreads();
        s[t] += tv;
        __syncthreads();
    }
    g_partials[t] = s[t];
    if (t == 0) g_rowptr[0] = 0;
}

__global__ void k_scan3() {
    int idx = blockIdx.x * 1024 + threadIdx.x;
    if (idx < NN) {
        int off = (blockIdx.x > 0) ? g_partials[blockIdx.x - 1] : 0;
        int incl = g_scanTmp[idx] + off;
        int excl = incl - g_counts[idx];
        g_rowptr[idx] = excl;
        g_cursor[idx] = excl;
        if (idx == NN - 1) g_rowptr[NN] = incl;
    }
}

__global__ void k_scatter(const int* __restrict__ ei) {
    int e = blockIdx.x * blockDim.x + threadIdx.x;
    if (e < NE) {
        int is64 = g_is64;
        int s = edge_at(ei, e, is64);
        unsigned d = (unsigned)edge_at(ei, (long long)NE + e, is64);
        if (d < NN) {
            int pos = atomicAdd(&g_cursor[d], 1);
            g_srcSorted[pos] = s;
        }
    }
}

// ---------------- packed fp32 -> (hi, lo) bf16x2 split ----------------
__device__ __forceinline__ void split2(float v0, float v1, uint32_t& h, uint32_t& l) {
    asm("cvt.rn.bf16x2.f32 %0, %1, %2;" : "=r"(h) : "f"(v1), "f"(v0));
    float h0 = __uint_as_float(h << 16);
    float h1 = __uint_as_float(h & 0xFFFF0000u);
    float l0 = v0 - h0, l1 = v1 - h1;
    asm("cvt.rn.bf16x2.f32 %0, %1, %2;" : "=r"(l) : "f"(l1), "f"(l0));
}

// ---------------- aggregation: warp per node, writes SPLIT planes ----------------
__global__ void k_agg64(const float* __restrict__ x, const float* __restrict__ epsp) {
    if (blockIdx.x == 0 && threadIdx.x < 128) {
        g_Ssum[threadIdx.x] = 0.f; g_Ssq[threadIdx.x] = 0.f;
    }
    int warp = (blockIdx.x * blockDim.x + threadIdx.x) >> 5;
    int lane = threadIdx.x & 31;
    if (warp >= NN) return;
    int lo = g_rowptr[warp], hi = g_rowptr[warp + 1];
    float eps1 = 1.0f + *epsp;
    const float2* xb = (const float2*)x;
    float2 self = xb[(size_t)warp * 32 + lane];
    float2 acc;
    acc.x = self.x * eps1; acc.y = self.y * eps1;
    for (int e = lo; e < hi; ++e) {
        int s = g_srcSorted[e];
        if ((unsigned)s < NN) {
            float2 v = xb[(size_t)s * 32 + lane];
            acc.x += v.x; acc.y += v.y;
        }
    }
    uint32_t h, l;
    split2(acc.x, acc.y, h, l);
    ((uint32_t*)g_bufAhi)[(size_t)warp * 32 + lane] = h;   // K=64: 32 words/row
    ((uint32_t*)g_bufAlo)[(size_t)warp * 32 + lane] = l;
}

__global__ void k_agg128(const float* __restrict__ epsp) {
    if (blockIdx.x == 0 && threadIdx.x < 128) {
        g_Ssum[threadIdx.x] = 0.f; g_Ssq[threadIdx.x] = 0.f;
    }
    int warp = (blockIdx.x * blockDim.x + threadIdx.x) >> 5;
    int lane = threadIdx.x & 31;
    if (warp >= NN) return;
    int lo = g_rowptr[warp], hi = g_rowptr[warp + 1];
    float eps1 = 1.0f + *epsp;
    const float4* xb = g_bufC;
    float4 self = xb[(size_t)warp * 32 + lane];
    float4 acc;
    acc.x = self.x * eps1; acc.y = self.y * eps1;
    acc.z = self.z * eps1; acc.w = self.w * eps1;
    for (int e = lo; e < hi; ++e) {
        int s = g_srcSorted[e];
        if ((unsigned)s < NN) {
            float4 v = xb[(size_t)s * 32 + lane];
            acc.x += v.x; acc.y += v.y; acc.z += v.z; acc.w += v.w;
        }
    }
    uint32_t h01, l01, h23, l23;
    split2(acc.x, acc.y, h01, l01);
    split2(acc.z, acc.w, h23, l23);
    ((uint2*)g_bufAhi)[(size_t)warp * 32 + lane] = make_uint2(h01, h23);  // K=128: 32 uint2/row
    ((uint2*)g_bufAlo)[(size_t)warp * 32 + lane] = make_uint2(l01, l23);
}

// ---------------- weight pre-split into fragment layout ----------------
__device__ __forceinline__ uint32_t pack_bf2(float a, float b) {
    uint32_t r;
    asm("cvt.rn.bf16x2.f32 %0, %1, %2;" : "=r"(r) : "f"(b), "f"(a));
    return r;
}

// slots: 0=wa0(K=64), 1..5 K=128, 6=hwa. W is [K][128] row-major fp32.
__global__ void k_prepAll(const float* __restrict__ w0, const float* __restrict__ w1,
                          const float* __restrict__ w2, const float* __restrict__ w3,
                          const float* __restrict__ w4, const float* __restrict__ w5,
                          const float* __restrict__ w6) {
    int slot = blockIdx.y;
    const float* W;
    int K;
    switch (slot) {
        case 0: W = w0; K = 64; break;
        case 1: W = w1; K = 128; break;
        case 2: W = w2; K = 128; break;
        case 3: W = w3; K = 128; break;
        case 4: W = w4; K = 128; break;
        case 5: W = w5; K = 128; break;
        default: W = w6; K = 128; break;
    }
    int idx = blockIdx.x * 256 + threadIdx.x;
    int NC = K / 16;
    if (idx >= NC * 512) return;
    int lane = idx & 31;
    int t = (idx >> 5) & 15;
    int c = idx >> 9;
    int qr = lane >> 2, qc = lane & 3;
    int nr = t * 8 + qr;
    int k0 = c * 16 + qc * 2;

    float v00 = W[(k0 + 0) * 128 + nr], v01 = W[(k0 + 1) * 128 + nr];
    float v10 = W[(k0 + 8) * 128 + nr], v11 = W[(k0 + 9) * 128 + nr];
    float h00 = __bfloat162float(__float2bfloat16(v00));
    float h01 = __bfloat162float(__float2bfloat16(v01));
    float h10 = __bfloat162float(__float2bfloat16(v10));
    float h11 = __bfloat162float(__float2bfloat16(v11));
    uint4 r;
    r.x = pack_bf2(v00, v01);
    r.y = pack_bf2(v10, v11);
    r.z = pack_bf2(v00 - h00, v01 - h01);
    r.w = pack_bf2(v10 - h10, v11 - h11);
    g_Wfrag[(size_t)slot * 4096 + idx] = r;
}

// ---------------- MMA primitive ----------------
__device__ __forceinline__ void mma_bf16(float* d, const uint32_t* a, const uint32_t* b) {
    asm volatile(
        "mma.sync.aligned.m16n8k16.row.col.f32.bf16.bf16.f32 "
        "{%0,%1,%2,%3}, {%4,%5,%6,%7}, {%8,%9}, {%0,%1,%2,%3};\n"
        : "+f"(d[0]), "+f"(d[1]), "+f"(d[2]), "+f"(d[3])
        : "r"(a[0]), "r"(a[1]), "r"(a[2]), "r"(a[3]), "r"(b[0]), "r"(b[1]));
}

// ---------------- A-tile staging (one 128x16 chunk) ----------------
// SRC: 0 = split planes (pure copy), 1 = g_bufB fp32 (+opt BN), 2 = g_bufC fp32
template<int K, int SRC, bool IN_BN>
__device__ __forceinline__ void stageA(
    __nv_bfloat16* dAhi, __nv_bfloat16* dAlo,
    const float* sScale, const float* sShift,
    int rowBase, int kk, int tid)
{
    if (SRC == 0) {
        // pre-split planes: 8 elems/thread, zero conversions
        int row = tid >> 1, half = tid & 1;
        int gr = rowBase + row;
        uint4 h = make_uint4(0, 0, 0, 0), l = make_uint4(0, 0, 0, 0);
        if (gr < NN) {
            size_t off = (size_t)gr * K + kk + half * 8;
            h = *(const uint4*)((const __nv_bfloat16*)g_bufAhi + off);
            l = *(const uint4*)((const __nv_bfloat16*)g_bufAlo + off);
        }
        *(uint4*)(dAhi + row * 16 + half * 8) = h;
        *(uint4*)(dAlo + row * 16 + half * 8) = l;
    } else {
        const float* A = (SRC == 1) ? (const float*)g_bufB : (const float*)g_bufC;
#pragma unroll
        for (int it = 0; it < 2; it++) {
            int f = it * 256 + tid;
            int row = f >> 2;
            int c4 = (f & 3) << 2;
            int gr = rowBase + row;
            float4 v = make_float4(0.f, 0.f, 0.f, 0.f);
            if (gr < NN) v = *(const float4*)(A + (size_t)gr * K + kk + c4);
            if (IN_BN) {
                int kb = kk + c4;
                v.x = fmaxf(v.x * sScale[kb + 0] + sShift[kb + 0], 0.f);
                v.y = fmaxf(v.y * sScale[kb + 1] + sShift[kb + 1], 0.f);
                v.z = fmaxf(v.z * sScale[kb + 2] + sShift[kb + 2], 0.f);
                v.w = fmaxf(v.w * sScale[kb + 3] + sShift[kb + 3], 0.f);
            }
            uint32_t h01, l01, h23, l23;
            split2(v.x, v.y, h01, l01);
            split2(v.z, v.w, h23, l23);
            *(uint2*)(dAhi + row * 16 + c4) = make_uint2(h01, h23);
            *(uint2*)(dAlo + row * 16 + c4) = make_uint2(l01, l23);
        }
    }
}

// =====================================================================
// split-bf16 GEMM, double-buffered staging (1 barrier / chunk).
// =====================================================================
template<int K, int SRC, int DST, int SLOT, bool IN_BN, bool OUT_RELU, bool STATS, bool HEAD>
__global__ void __launch_bounds__(256)
k_gemm_mma(const float* __restrict__ bias, const float* __restrict__ gamma,
           const float* __restrict__ beta, const float* __restrict__ hwb,
           const float* __restrict__ hbb, float* __restrict__ outp) {
    constexpr int NC = K / 16;
    const uint4* pW = g_Wfrag + (size_t)SLOT * 4096;

    __shared__ __align__(16) __nv_bfloat16 sAhi[2][128 * 16];
    __shared__ __align__(16) __nv_bfloat16 sAlo[2][128 * 16];
    __shared__ float sSum[128], sSq[128];
    __shared__ float sScale[128], sShift[128];
    __shared__ float sOut[256];              // HEAD epilogue only

    const int tid = threadIdx.x;
    const int lane = tid & 31;
    const int warp = tid >> 5;
    const int wm = warp & 3;
    const int wn = warp >> 2;
    const int qr = lane >> 2;
    const int qc = lane & 3;
    const int rowBase = blockIdx.x * 128;

    if (STATS && tid < 128) { sSum[tid] = 0.f; sSq[tid] = 0.f; }
    if (HEAD) sOut[tid] = 0.f;
    if (IN_BN) {
        if (tid < 128) {
            float mu = g_Ssum[tid] * (1.0f / NN);
            float var = fmaxf(g_Ssq[tid] * (1.0f / NN) - mu * mu, 0.f);
            float sc = gamma[tid] * rsqrtf(var + 1e-5f);
            sScale[tid] = sc;
            sShift[tid] = beta[tid] - mu * sc;
        }
        __syncthreads();
    }

    float acc[2][8][4];
#pragma unroll
    for (int m = 0; m < 2; m++)
#pragma unroll
        for (int n = 0; n < 8; n++)
#pragma unroll
            for (int j = 0; j < 4; j++) acc[m][n][j] = 0.f;

    // prologue: stage chunk 0
    stageA<K, SRC, IN_BN>(sAhi[0], sAlo[0], sScale, sShift, rowBase, 0, tid);
    __syncthreads();

#pragma unroll
    for (int c = 0; c < NC; c++) {
        // stage next chunk into alternate buffer (overlaps with MMAs below)
        if (c + 1 < NC)
            stageA<K, SRC, IN_BN>(sAhi[(c + 1) & 1], sAlo[(c + 1) & 1],
                                  sScale, sShift, rowBase, (c + 1) * 16, tid);

        const uint32_t* a32h = (const uint32_t*)sAhi[c & 1];
        const uint32_t* a32l = (const uint32_t*)sAlo[c & 1];
        uint4 bf[8];
#pragma unroll
        for (int n = 0; n < 8; n++)
            bf[n] = pW[(size_t)((c * 16 + wn * 8 + n) * 32 + lane)];

#pragma unroll
        for (int m = 0; m < 2; m++) {
            int r = wm * 32 + m * 16 + qr;
            uint32_t ah[4], al[4];
            ah[0] = a32h[r * 8 + qc];
            ah[1] = a32h[(r + 8) * 8 + qc];
            ah[2] = a32h[r * 8 + 4 + qc];
            ah[3] = a32h[(r + 8) * 8 + 4 + qc];
            al[0] = a32l[r * 8 + qc];
            al[1] = a32l[(r + 8) * 8 + qc];
            al[2] = a32l[r * 8 + 4 + qc];
            al[3] = a32l[(r + 8) * 8 + 4 + qc];
#pragma unroll
            for (int n = 0; n < 8; n++) {
                uint32_t bh[2] = {bf[n].x, bf[n].y};
                uint32_t bl[2] = {bf[n].z, bf[n].w};
                mma_bf16(acc[m][n], ah, bh);
                mma_bf16(acc[m][n], ah, bl);
                mma_bf16(acc[m][n], al, bh);
            }
        }
        __syncthreads();
    }

    // ---- epilogue ----
    if (HEAD) {
#pragma unroll
        for (int m = 0; m < 2; m++) {
            int rl = wm * 32 + m * 16 + qr;
#pragma unroll
            for (int n = 0; n < 8; n++) {
                int cc = wn * 64 + n * 8 + qc * 2;
                float b0 = bias[cc], b1 = bias[cc + 1];
                float v0 = fmaxf(acc[m][n][0] + b0, 0.f), v1 = fmaxf(acc[m][n][1] + b1, 0.f);
                float v2 = fmaxf(acc[m][n][2] + b0, 0.f), v3 = fmaxf(acc[m][n][3] + b1, 0.f);
                float w00 = hwb[cc * 2 + 0], w01 = hwb[cc * 2 + 1];
                float w10 = hwb[(cc + 1) * 2 + 0], w11 = hwb[(cc + 1) * 2 + 1];
                if (rowBase + rl < NN) {
                    atomicAdd(&sOut[rl * 2 + 0], v0 * w00 + v1 * w10);
                    atomicAdd(&sOut[rl * 2 + 1], v0 * w01 + v1 * w11);
                }
                if (rowBase + rl + 8 < NN) {
                    atomicAdd(&sOut[(rl + 8) * 2 + 0], v2 * w00 + v3 * w10);
                    atomicAdd(&sOut[(rl + 8) * 2 + 1], v2 * w01 + v3 * w11);
                }
            }
        }
        __syncthreads();
        if (tid < 128) {
            int r = rowBase + tid;
            if (r < NN) {
                outp[(size_t)r * 2 + 0] = sOut[tid * 2 + 0] + hbb[0];
                outp[(size_t)r * 2 + 1] = sOut[tid * 2 + 1] + hbb[1];
            }
        }
        return;
    }

    float* out = (DST == 1) ? (float*)g_bufB : (float*)g_bufC;
    float cS[16], cQ[16];
    if (STATS) {
#pragma unroll
        for (int j = 0; j < 16; j++) { cS[j] = 0.f; cQ[j] = 0.f; }
    }

#pragma unroll
    for (int m = 0; m < 2; m++) {
        int r = rowBase + wm * 32 + m * 16 + qr;
#pragma unroll
        for (int n = 0; n < 8; n++) {
            int cc = wn * 64 + n * 8 + qc * 2;
            float b0 = bias[cc], b1 = bias[cc + 1];
            float v0 = acc[m][n][0] + b0, v1 = acc[m][n][1] + b1;
            float v2 = acc[m][n][2] + b0, v3 = acc[m][n][3] + b1;
            if (OUT_RELU) {
                v0 = fmaxf(v0, 0.f); v1 = fmaxf(v1, 0.f);
                v2 = fmaxf(v2, 0.f); v3 = fmaxf(v3, 0.f);
            }
            if (r < NN) {
                *(float2*)(out + (size_t)r * 128 + cc) = make_float2(v0, v1);
                if (STATS) {
                    cS[n * 2] += v0; cS[n * 2 + 1] += v1;
                    cQ[n * 2] += v0 * v0; cQ[n * 2 + 1] += v1 * v1;
                }
            }
            if (r + 8 < NN) {
                *(float2*)(out + (size_t)(r + 8) * 128 + cc) = make_float2(v2, v3);
                if (STATS) {
                    cS[n * 2] += v2; cS[n * 2 + 1] += v3;
                    cQ[n * 2] += v2 * v2; cQ[n * 2 + 1] += v3 * v3;
                }
            }
        }
    }

    if (STATS) {
#pragma unroll
        for (int n = 0; n < 8; n++) {
            int cc = wn * 64 + n * 8 + qc * 2;
            atomicAdd(&sSum[cc], cS[n * 2]);
            atomicAdd(&sSum[cc + 1], cS[n * 2 + 1]);
            atomicAdd(&sSq[cc], cQ[n * 2]);
            atomicAdd(&sSq[cc + 1], cQ[n * 2 + 1]);
        }
        __syncthreads();
        if (tid < 128) {
            atomicAdd(&g_Ssum[tid], sSum[tid]);
            atomicAdd(&g_Ssq[tid], sSq[tid]);
        }
    }
}

// ---------------- launch ----------------
extern "C" void kernel_launch(void* const* d_in, const int* in_sizes, int n_in,
                              void* d_out, int out_size) {
    const float* x = (const float*)d_in[0];
    const int* ei = (const int*)d_in[1];

    const float* wa[3]; const float* ba[3]; const float* gm[3]; const float* be[3];
    const float* wb[3]; const float* bb[3]; const float* ep[3];
    for (int l = 0; l < 3; l++) {
        int b = 2 + 7 * l;
        wa[l] = (const float*)d_in[b + 0];
        ba[l] = (const float*)d_in[b + 1];
        gm[l] = (const float*)d_in[b + 2];
        be[l] = (const float*)d_in[b + 3];
        wb[l] = (const float*)d_in[b + 4];
        bb[l] = (const float*)d_in[b + 5];
        ep[l] = (const float*)d_in[b + 6];
    }
    const float* hwa = (const float*)d_in[23];
    const float* hba = (const float*)d_in[24];
    const float* hwb = (const float*)d_in[25];
    const float* hbb = (const float*)d_in[26];
    float* out = (float*)d_out;

    const int NB1 = (NN + 1023) / 1024;       // 98
    const int GB = (NN + 127) / 128;           // 782
    const int AGGB = (NN + 7) / 8;             // 12500

    // one-shot weight pre-split (K=128 slots need 4096 threads -> 16 blocks)
    dim3 pg(16, 7);
    k_prepAll<<<pg, 256>>>(wa[0], wb[0], wa[1], wb[1], wa[2], wb[2], hwa);

    // edge dtype detection + CSR build
    k_detect<<<1, 256>>>(ei);
    k_zero_counts<<<(NN + 255) / 256, 256>>>();
    k_hist<<<(NE + 255) / 256, 256>>>(ei);
    k_scan1<<<NB1, 1024>>>();
    k_scan2<<<1, 128>>>(NB1);
    k_scan3<<<NB1, 1024>>>();
    k_scatter<<<(NE + 255) / 256, 256>>>(ei);

    // ---- layer 0 (din = 64): x -> Ahi/Alo -> bufB -> bufC ----
    k_agg64<<<AGGB, 256>>>(x, ep[0]);
    k_gemm_mma<64, 0, 1, 0, false, false, true, false><<<GB, 256>>>(
        ba[0], nullptr, nullptr, nullptr, nullptr, nullptr);
    k_gemm_mma<128, 1, 2, 1, true, true, false, false><<<GB, 256>>>(
        bb[0], gm[0], be[0], nullptr, nullptr, nullptr);

    // ---- layer 1 ----
    k_agg128<<<AGGB, 256>>>(ep[1]);
    k_gemm_mma<128, 0, 1, 2, false, false, true, false><<<GB, 256>>>(
        ba[1], nullptr, nullptr, nullptr, nullptr, nullptr);
    k_gemm_mma<128, 1, 2, 3, true, true, false, false><<<GB, 256>>>(
        bb[1], gm[1], be[1], nullptr, nullptr, nullptr);

    // ---- layer 2 ----
    k_agg128<<<AGGB, 256>>>(ep[2]);
    k_gemm_mma<128, 0, 1, 4, false, false, true, false><<<GB, 256>>>(
        ba[2], nullptr, nullptr, nullptr, nullptr, nullptr);
    k_gemm_mma<128, 1, 2, 5, true, true, false, false><<<GB, 256>>>(
        bb[2], gm[2], be[2], nullptr, nullptr, nullptr);

    // ---- fused head: bufC -> out ----
    k_gemm_mma<128, 2, 2, 6, false, false, false, true><<<GB, 256>>>(
        hba, nullptr, nullptr, hwb, hbb, out);
}

// round 14
// speedup vs baseline: 1.9320x; 1.9320x over previous
#include <cuda_runtime.h>
#include <cuda_bf16.h>
#include <cstdint>

#define NN 100000
#define NE 1600000
#define HDIM 128

// ---------------- static device scratch ----------------
__device__ uint4 g_bufAhi[(size_t)NN * 16];  // agg output, hi bf16 plane (N x K)
__device__ uint4 g_bufAlo[(size_t)NN * 16];  // agg output, lo bf16 plane
__device__ float4 g_bufB[(size_t)NN * 32];   // pre-BN linear output (fp32)
__device__ float4 g_bufC[(size_t)NN * 32];   // layer outputs (fp32)

__device__ int g_counts[NN];
__device__ int g_scanTmp[NN];
__device__ int g_partials[128];
__device__ int g_rowptr[NN + 1];
__device__ int g_cursor[NN];
__device__ int g_srcSorted[NE];
__device__ int g_is64;

__device__ float g_Ssum[HDIM];
__device__ float g_Ssq[HDIM];

// Pre-swizzled B fragments: slot s, chunk c (k/16), ntile t (n/8), lane.
// uint4 = {bh_reg0, bh_reg1, bl_reg0, bl_reg1} for mma m16n8k16 (split bf16).
__device__ uint4 g_Wfrag[7 * 4096];

__device__ __forceinline__ int edge_at(const int* __restrict__ ei, long long pos, int is64) {
    return is64 ? ei[2 * pos] : ei[(size_t)pos];
}

// ---------------- dtype detector ----------------
__global__ void k_detect(const int* __restrict__ ei) {
    __shared__ int nz;
    if (threadIdx.x == 0) nz = 0;
    __syncthreads();
    long long p = (long long)threadIdx.x * (NE / 256);
    if (ei[2 * p + 1] != 0) atomicAdd(&nz, 1);
    __syncthreads();
    if (threadIdx.x == 0) g_is64 = (nz == 0) ? 1 : 0;
}

// ---------------- CSR build ----------------
__global__ void k_zero_counts() {
    int i = blockIdx.x * blockDim.x + threadIdx.x;
    if (i < NN) g_counts[i] = 0;
}

__global__ void k_hist(const int* __restrict__ ei) {
    int e = blockIdx.x * blockDim.x + threadIdx.x;
    if (e < NE) {
        int is64 = g_is64;
        unsigned d = (unsigned)edge_at(ei, (long long)NE + e, is64);
        if (d < NN) atomicAdd(&g_counts[d], 1);
    }
}

__global__ void k_scan1() {
    __shared__ int s[1024];
    int idx = blockIdx.x * 1024 + threadIdx.x;
    int v = (idx < NN) ? g_counts[idx] : 0;
    s[threadIdx.x] = v;
    __syncthreads();
    for (int off = 1; off < 1024; off <<= 1) {
        int t = 0;
        if (threadIdx.x >= off) t = s[threadIdx.x - off];
        __syncthreads();
        s[threadIdx.x] += t;
        __syncthreads();
    }
    if (idx < NN) g_scanTmp[idx] = s[threadIdx.x];
    if (threadIdx.x == 1023) g_partials[blockIdx.x] = s[1023];
}

__global__ void k_scan2(int nblocks) {
    __shared__ int s[128];
    int t = threadIdx.x;
    int v = (t < nblocks) ? g_partials[t] : 0;
    s[t] = v;
    __syncthreads();
    for (int off = 1; off < 128; off <<= 1) {
        int tv = 0;
        if (t >= off) tv = s[t - off];
        __syncthreads();
        s[t] += tv;
        __syncthreads();
    }
    g_partials[t] = s[t];
    if (t == 0) g_rowptr[0] = 0;
}

__global__ void k_scan3() {
    int idx = blockIdx.x * 1024 + threadIdx.x;
    if (idx < NN) {
        int off = (blockIdx.x > 0) ? g_partials[blockIdx.x - 1] : 0;
        int incl = g_scanTmp[idx] + off;
        int excl = incl - g_counts[idx];
        g_rowptr[idx] = excl;
        g_cursor[idx] = excl;
        if (idx == NN - 1) g_rowptr[NN] = incl;
    }
}

__global__ void k_scatter(const int* __restrict__ ei) {
    int e = blockIdx.x * blockDim.x + threadIdx.x;
    if (e < NE) {
        int is64 = g_is64;
        int s = edge_at(ei, e, is64);
        unsigned d = (unsigned)edge_at(ei, (long long)NE + e, is64);
        if (d < NN) {
            int pos = atomicAdd(&g_cursor[d], 1);
            g_srcSorted[pos] = s;
        }
    }
}

// ---------------- packed fp32 -> (hi, lo) bf16x2 split ----------------
__device__ __forceinline__ void split2(float v0, float v1, uint32_t& h, uint32_t& l) {
    asm("cvt.rn.bf16x2.f32 %0, %1, %2;" : "=r"(h) : "f"(v1), "f"(v0));
    float h0 = __uint_as_float(h << 16);
    float h1 = __uint_as_float(h & 0xFFFF0000u);
    float l0 = v0 - h0, l1 = v1 - h1;
    asm("cvt.rn.bf16x2.f32 %0, %1, %2;" : "=r"(l) : "f"(l1), "f"(l0));
}

// ---------------- aggregation: warp per node, writes SPLIT planes ----------------
__global__ void k_agg64(const float* __restrict__ x, const float* __restrict__ epsp) {
    if (blockIdx.x == 0 && threadIdx.x < 128) {
        g_Ssum[threadIdx.x] = 0.f; g_Ssq[threadIdx.x] = 0.f;
    }
    int warp = (blockIdx.x * blockDim.x + threadIdx.x) >> 5;
    int lane = threadIdx.x & 31;
    if (warp >= NN) return;
    int lo = g_rowptr[warp], hi = g_rowptr[warp + 1];
    float eps1 = 1.0f + *epsp;
    const float2* xb = (const float2*)x;
    float2 self = xb[(size_t)warp * 32 + lane];
    float2 acc;
    acc.x = self.x * eps1; acc.y = self.y * eps1;
    for (int e = lo; e < hi; ++e) {
        int s = g_srcSorted[e];
        if ((unsigned)s < NN) {
            float2 v = xb[(size_t)s * 32 + lane];
            acc.x += v.x; acc.y += v.y;
        }
    }
    uint32_t h, l;
    split2(acc.x, acc.y, h, l);
    ((uint32_t*)g_bufAhi)[(size_t)warp * 32 + lane] = h;   // K=64: 32 words/row
    ((uint32_t*)g_bufAlo)[(size_t)warp * 32 + lane] = l;
}

__global__ void k_agg128(const float* __restrict__ epsp) {
    if (blockIdx.x == 0 && threadIdx.x < 128) {
        g_Ssum[threadIdx.x] = 0.f; g_Ssq[threadIdx.x] = 0.f;
    }
    int warp = (blockIdx.x * blockDim.x + threadIdx.x) >> 5;
    int lane = threadIdx.x & 31;
    if (warp >= NN) return;
    int lo = g_rowptr[warp], hi = g_rowptr[warp + 1];
    float eps1 = 1.0f + *epsp;
    const float4* xb = g_bufC;
    float4 self = xb[(size_t)warp * 32 + lane];
    float4 acc;
    acc.x = self.x * eps1; acc.y = self.y * eps1;
    acc.z = self.z * eps1; acc.w = self.w * eps1;
    for (int e = lo; e < hi; ++e) {
        int s = g_srcSorted[e];
        if ((unsigned)s < NN) {
            float4 v = xb[(size_t)s * 32 + lane];
            acc.x += v.x; acc.y += v.y; acc.z += v.z; acc.w += v.w;
        }
    }
    uint32_t h01, l01, h23, l23;
    split2(acc.x, acc.y, h01, l01);
    split2(acc.z, acc.w, h23, l23);
    ((uint2*)g_bufAhi)[(size_t)warp * 32 + lane] = make_uint2(h01, h23);  // 32 uint2/row
    ((uint2*)g_bufAlo)[(size_t)warp * 32 + lane] = make_uint2(l01, l23);
}

// ---------------- weight pre-split into fragment layout ----------------
__device__ __forceinline__ uint32_t pack_bf2(float a, float b) {
    uint32_t r;
    asm("cvt.rn.bf16x2.f32 %0, %1, %2;" : "=r"(r) : "f"(b), "f"(a));
    return r;
}

// slots: 0=wa0(K=64), 1..5 K=128, 6=hwa. W is [K][128] row-major fp32.
__global__ void k_prepAll(const float* __restrict__ w0, const float* __restrict__ w1,
                          const float* __restrict__ w2, const float* __restrict__ w3,
                          const float* __restrict__ w4, const float* __restrict__ w5,
                          const float* __restrict__ w6) {
    int slot = blockIdx.y;
    const float* W;
    int K;
    switch (slot) {
        case 0: W = w0; K = 64; break;
        case 1: W = w1; K = 128; break;
        case 2: W = w2; K = 128; break;
        case 3: W = w3; K = 128; break;
        case 4: W = w4; K = 128; break;
        case 5: W = w5; K = 128; break;
        default: W = w6; K = 128; break;
    }
    int idx = blockIdx.x * 256 + threadIdx.x;
    int NC = K / 16;
    if (idx >= NC * 512) return;
    int lane = idx & 31;
    int t = (idx >> 5) & 15;
    int c = idx >> 9;
    int qr = lane >> 2, qc = lane & 3;
    int nr = t * 8 + qr;
    int k0 = c * 16 + qc * 2;

    float v00 = W[(k0 + 0) * 128 + nr], v01 = W[(k0 + 1) * 128 + nr];
    float v10 = W[(k0 + 8) * 128 + nr], v11 = W[(k0 + 9) * 128 + nr];
    float h00 = __bfloat162float(__float2bfloat16(v00));
    float h01 = __bfloat162float(__float2bfloat16(v01));
    float h10 = __bfloat162float(__float2bfloat16(v10));
    float h11 = __bfloat162float(__float2bfloat16(v11));
    uint4 r;
    r.x = pack_bf2(v00, v01);
    r.y = pack_bf2(v10, v11);
    r.z = pack_bf2(v00 - h00, v01 - h01);
    r.w = pack_bf2(v10 - h10, v11 - h11);
    g_Wfrag[(size_t)slot * 4096 + idx] = r;
}

// ---------------- MMA primitive ----------------
__device__ __forceinline__ void mma_bf16(float* d, const uint32_t* a, const uint32_t* b) {
    asm volatile(
        "mma.sync.aligned.m16n8k16.row.col.f32.bf16.bf16.f32 "
        "{%0,%1,%2,%3}, {%4,%5,%6,%7}, {%8,%9}, {%0,%1,%2,%3};\n"
        : "+f"(d[0]), "+f"(d[1]), "+f"(d[2]), "+f"(d[3])
        : "r"(a[0]), "r"(a[1]), "r"(a[2]), "r"(a[3]), "r"(b[0]), "r"(b[1]));
}

// =====================================================================
// split-bf16 GEMM — R12 single-buffer schedule.
// SRC: 0 = pre-split planes (copy staging), 1 = g_bufB fp32 (+BN), 2 = g_bufC fp32
// =====================================================================
template<int K, int SRC, int DST, int SLOT, bool IN_BN, bool OUT_RELU, bool STATS, bool HEAD>
__global__ void __launch_bounds__(256)
k_gemm_mma(const float* __restrict__ bias, const float* __restrict__ gamma,
           const float* __restrict__ beta, const float* __restrict__ hwb,
           const float* __restrict__ hbb, float* __restrict__ outp) {
    const uint4* pW = g_Wfrag + (size_t)SLOT * 4096;

    __shared__ __align__(16) __nv_bfloat16 sAhi[128 * 16];
    __shared__ __align__(16) __nv_bfloat16 sAlo[128 * 16];
    __shared__ float sSum[128], sSq[128];
    __shared__ float sScale[128], sShift[128];
    __shared__ float sOut[256];              // HEAD epilogue only

    const int tid = threadIdx.x;
    const int lane = tid & 31;
    const int warp = tid >> 5;
    const int wm = warp & 3;
    const int wn = warp >> 2;
    const int qr = lane >> 2;
    const int qc = lane & 3;
    const int rowBase = blockIdx.x * 128;

    if (STATS && tid < 128) { sSum[tid] = 0.f; sSq[tid] = 0.f; }
    if (HEAD) sOut[tid] = 0.f;
    if (IN_BN) {
        if (tid < 128) {
            float mu = g_Ssum[tid] * (1.0f / NN);
            float var = fmaxf(g_Ssq[tid] * (1.0f / NN) - mu * mu, 0.f);
            float sc = gamma[tid] * rsqrtf(var + 1e-5f);
            sScale[tid] = sc;
            sShift[tid] = beta[tid] - mu * sc;
        }
        __syncthreads();
    }

    float acc[2][8][4];
#pragma unroll
    for (int m = 0; m < 2; m++)
#pragma unroll
        for (int n = 0; n < 8; n++)
#pragma unroll
            for (int j = 0; j < 4; j++) acc[m][n][j] = 0.f;

    for (int kk = 0; kk < K; kk += 16) {
        // ---- stage A tile 128x16 ----
        if (SRC == 0) {
            // pre-split planes: pure uint4 copy, zero conversions
            int row = tid >> 1, half = tid & 1;
            int gr = rowBase + row;
            uint4 h = make_uint4(0, 0, 0, 0), l = make_uint4(0, 0, 0, 0);
            if (gr < NN) {
                size_t off = (size_t)gr * K + kk + half * 8;
                h = *(const uint4*)((const __nv_bfloat16*)g_bufAhi + off);
                l = *(const uint4*)((const __nv_bfloat16*)g_bufAlo + off);
            }
            *(uint4*)(sAhi + row * 16 + half * 8) = h;
            *(uint4*)(sAlo + row * 16 + half * 8) = l;
        } else {
            const float* A = (SRC == 1) ? (const float*)g_bufB : (const float*)g_bufC;
#pragma unroll
            for (int it = 0; it < 2; it++) {
                int f = it * 256 + tid;
                int row = f >> 2;
                int c4 = (f & 3) << 2;
                int gr = rowBase + row;
                float4 v = make_float4(0.f, 0.f, 0.f, 0.f);
                if (gr < NN) v = *(const float4*)(A + (size_t)gr * K + kk + c4);
                if (IN_BN) {
                    int kb = kk + c4;
                    v.x = fmaxf(v.x * sScale[kb + 0] + sShift[kb + 0], 0.f);
                    v.y = fmaxf(v.y * sScale[kb + 1] + sShift[kb + 1], 0.f);
                    v.z = fmaxf(v.z * sScale[kb + 2] + sShift[kb + 2], 0.f);
                    v.w = fmaxf(v.w * sScale[kb + 3] + sShift[kb + 3], 0.f);
                }
                uint32_t h01, l01, h23, l23;
                split2(v.x, v.y, h01, l01);
                split2(v.z, v.w, h23, l23);
                *(uint2*)(sAhi + row * 16 + c4) = make_uint2(h01, h23);
                *(uint2*)(sAlo + row * 16 + c4) = make_uint2(l01, l23);
            }
        }
        __syncthreads();

        const uint32_t* a32h = (const uint32_t*)sAhi;
        const uint32_t* a32l = (const uint32_t*)sAlo;
        int c = kk / 16;
        uint4 bf[8];
#pragma unroll
        for (int n = 0; n < 8; n++)
            bf[n] = pW[(size_t)((c * 16 + wn * 8 + n) * 32 + lane)];

#pragma unroll
        for (int m = 0; m < 2; m++) {
            int r = wm * 32 + m * 16 + qr;
            uint32_t ah[4], al[4];
            ah[0] = a32h[r * 8 + qc];
            ah[1] = a32h[(r + 8) * 8 + qc];
            ah[2] = a32h[r * 8 + 4 + qc];
            ah[3] = a32h[(r + 8) * 8 + 4 + qc];
            al[0] = a32l[r * 8 + qc];
            al[1] = a32l[(r + 8) * 8 + qc];
            al[2] = a32l[r * 8 + 4 + qc];
            al[3] = a32l[(r + 8) * 8 + 4 + qc];
#pragma unroll
            for (int n = 0; n < 8; n++) {
                uint32_t bh[2] = {bf[n].x, bf[n].y};
                uint32_t bl[2] = {bf[n].z, bf[n].w};
                mma_bf16(acc[m][n], ah, bh);
                mma_bf16(acc[m][n], ah, bl);
                mma_bf16(acc[m][n], al, bh);
            }
        }
        __syncthreads();
    }

    // ---- epilogue ----
    if (HEAD) {
#pragma unroll
        for (int m = 0; m < 2; m++) {
            int rl = wm * 32 + m * 16 + qr;
#pragma unroll
            for (int n = 0; n < 8; n++) {
                int cc = wn * 64 + n * 8 + qc * 2;
                float b0 = bias[cc], b1 = bias[cc + 1];
                float v0 = fmaxf(acc[m][n][0] + b0, 0.f), v1 = fmaxf(acc[m][n][1] + b1, 0.f);
                float v2 = fmaxf(acc[m][n][2] + b0, 0.f), v3 = fmaxf(acc[m][n][3] + b1, 0.f);
                float w00 = hwb[cc * 2 + 0], w01 = hwb[cc * 2 + 1];
                float w10 = hwb[(cc + 1) * 2 + 0], w11 = hwb[(cc + 1) * 2 + 1];
                if (rowBase + rl < NN) {
                    atomicAdd(&sOut[rl * 2 + 0], v0 * w00 + v1 * w10);
                    atomicAdd(&sOut[rl * 2 + 1], v0 * w01 + v1 * w11);
                }
                if (rowBase + rl + 8 < NN) {
                    atomicAdd(&sOut[(rl + 8) * 2 + 0], v2 * w00 + v3 * w10);
                    atomicAdd(&sOut[(rl + 8) * 2 + 1], v2 * w01 + v3 * w11);
                }
            }
        }
        __syncthreads();
        if (tid < 128) {
            int r = rowBase + tid;
            if (r < NN) {
                outp[(size_t)r * 2 + 0] = sOut[tid * 2 + 0] + hbb[0];
                outp[(size_t)r * 2 + 1] = sOut[tid * 2 + 1] + hbb[1];
            }
        }
        return;
    }

    float* out = (DST == 1) ? (float*)g_bufB : (float*)g_bufC;
    float cS[16], cQ[16];
    if (STATS) {
#pragma unroll
        for (int j = 0; j < 16; j++) { cS[j] = 0.f; cQ[j] = 0.f; }
    }

#pragma unroll
    for (int m = 0; m < 2; m++) {
        int r = rowBase + wm * 32 + m * 16 + qr;
#pragma unroll
        for (int n = 0; n < 8; n++) {
            int cc = wn * 64 + n * 8 + qc * 2;
            float b0 = bias[cc], b1 = bias[cc + 1];
            float v0 = acc[m][n][0] + b0, v1 = acc[m][n][1] + b1;
            float v2 = acc[m][n][2] + b0, v3 = acc[m][n][3] + b1;
            if (OUT_RELU) {
                v0 = fmaxf(v0, 0.f); v1 = fmaxf(v1, 0.f);
                v2 = fmaxf(v2, 0.f); v3 = fmaxf(v3, 0.f);
            }
            if (r < NN) {
                *(float2*)(out + (size_t)r * 128 + cc) = make_float2(v0, v1);
                if (STATS) {
                    cS[n * 2] += v0; cS[n * 2 + 1] += v1;
                    cQ[n * 2] += v0 * v0; cQ[n * 2 + 1] += v1 * v1;
                }
            }
            if (r + 8 < NN) {
                *(float2*)(out + (size_t)(r + 8) * 128 + cc) = make_float2(v2, v3);
                if (STATS) {
                    cS[n * 2] += v2; cS[n * 2 + 1] += v3;
                    cQ[n * 2] += v2 * v2; cQ[n * 2 + 1] += v3 * v3;
                }
            }
        }
    }

    if (STATS) {
#pragma unroll
        for (int n = 0; n < 8; n++) {
            int cc = wn * 64 + n * 8 + qc * 2;
            atomicAdd(&sSum[cc], cS[n * 2]);
            atomicAdd(&sSum[cc + 1], cS[n * 2 + 1]);
            atomicAdd(&sSq[cc], cQ[n * 2]);
            atomicAdd(&sSq[cc + 1], cQ[n * 2 + 1]);
        }
        __syncthreads();
        if (tid < 128) {
            atomicAdd(&g_Ssum[tid], sSum[tid]);
            atomicAdd(&g_Ssq[tid], sSq[tid]);
        }
    }
}

// ---------------- launch ----------------
extern "C" void kernel_launch(void* const* d_in, const int* in_sizes, int n_in,
                              void* d_out, int out_size) {
    const float* x = (const float*)d_in[0];
    const int* ei = (const int*)d_in[1];

    const float* wa[3]; const float* ba[3]; const float* gm[3]; const float* be[3];
    const float* wb[3]; const float* bb[3]; const float* ep[3];
    for (int l = 0; l < 3; l++) {
        int b = 2 + 7 * l;
        wa[l] = (const float*)d_in[b + 0];
        ba[l] = (const float*)d_in[b + 1];
        gm[l] = (const float*)d_in[b + 2];
        be[l] = (const float*)d_in[b + 3];
        wb[l] = (const float*)d_in[b + 4];
        bb[l] = (const float*)d_in[b + 5];
        ep[l] = (const float*)d_in[b + 6];
    }
    const float* hwa = (const float*)d_in[23];
    const float* hba = (const float*)d_in[24];
    const float* hwb = (const float*)d_in[25];
    const float* hbb = (const float*)d_in[26];
    float* out = (float*)d_out;

    const int NB1 = (NN + 1023) / 1024;       // 98
    const int GB = (NN + 127) / 128;           // 782
    const int AGGB = (NN + 7) / 8;             // 12500

    // one-shot weight pre-split (K=128 slots need 4096 threads -> 16 blocks)
    dim3 pg(16, 7);
    k_prepAll<<<pg, 256>>>(wa[0], wb[0], wa[1], wb[1], wa[2], wb[2], hwa);

    // edge dtype detection + CSR build
    k_detect<<<1, 256>>>(ei);
    k_zero_counts<<<(NN + 255) / 256, 256>>>();
    k_hist<<<(NE + 255) / 256, 256>>>(ei);
    k_scan1<<<NB1, 1024>>>();
    k_scan2<<<1, 128>>>(NB1);
    k_scan3<<<NB1, 1024>>>();
    k_scatter<<<(NE + 255) / 256, 256>>>(ei);

    // ---- layer 0 (din = 64): x -> Ahi/Alo -> bufB -> bufC ----
    k_agg64<<<AGGB, 256>>>(x, ep[0]);
    k_gemm_mma<64, 0, 1, 0, false, false, true, false><<<GB, 256>>>(
        ba[0], nullptr, nullptr, nullptr, nullptr, nullptr);
    k_gemm_mma<128, 1, 2, 1, true, true, false, false><<<GB, 256>>>(
        bb[0], gm[0], be[0], nullptr, nullptr, nullptr);

    // ---- layer 1 ----
    k_agg128<<<AGGB, 256>>>(ep[1]);
    k_gemm_mma<128, 0, 1, 2, false, false, true, false><<<GB, 256>>>(
        ba[1], nullptr, nullptr, nullptr, nullptr, nullptr);
    k_gemm_mma<128, 1, 2, 3, true, true, false, false><<<GB, 256>>>(
        bb[1], gm[1], be[1], nullptr, nullptr, nullptr);

    // ---- layer 2 ----
    k_agg128<<<AGGB, 256>>>(ep[2]);
    k_gemm_mma<128, 0, 1, 4, false, false, true, false><<<GB, 256>>>(
        ba[2], nullptr, nullptr, nullptr, nullptr, nullptr);
    k_gemm_mma<128, 1, 2, 5, true, true, false, false><<<GB, 256>>>(
        bb[2], gm[2], be[2], nullptr, nullptr, nullptr);

    // ---- fused head: bufC -> out ----
    k_gemm_mma<128, 2, 2, 6, false, false, false, true><<<GB, 256>>>(
        hba, nullptr, nullptr, hwb, hbb, out);
}

// round 15
// speedup vs baseline: 1.9552x; 1.0120x over previous
#include <cuda_runtime.h>
#include <cuda_bf16.h>
#include <cstdint>

#define NN 100000
#define NE 1600000
#define HDIM 128

// ---------------- static device scratch ----------------
__device__ uint4 g_bufAhi[(size_t)NN * 16];  // agg output, hi bf16 plane (N x K)
__device__ uint4 g_bufAlo[(size_t)NN * 16];  // agg output, lo bf16 plane
__device__ float4 g_bufB[(size_t)NN * 32];   // pre-BN linear output (fp32)
__device__ float4 g_bufC[(size_t)NN * 32];   // layer outputs (fp32)

__device__ int g_counts[NN];
__device__ int g_scanTmp[NN];
__device__ int g_partials[128];
__device__ int g_rowptr[NN + 1];
__device__ int g_cursor[NN];
__device__ int g_srcSorted[NE];
__device__ int g_is64;

__device__ float g_Ssum[HDIM];
__device__ float g_Ssq[HDIM];

// Pre-swizzled B fragments: slot s, chunk c (k/16), ntile t (n/8), lane.
// uint4 = {bh_reg0, bh_reg1, bl_reg0, bl_reg1} for mma m16n8k16 (split bf16).
__device__ uint4 g_Wfrag[7 * 4096];

__device__ __forceinline__ int edge_at(const int* __restrict__ ei, long long pos, int is64) {
    return is64 ? ei[2 * pos] : ei[(size_t)pos];
}

// ---------------- dtype detector ----------------
__global__ void k_detect(const int* __restrict__ ei) {
    __shared__ int nz;
    if (threadIdx.x == 0) nz = 0;
    __syncthreads();
    long long p = (long long)threadIdx.x * (NE / 256);
    if (ei[2 * p + 1] != 0) atomicAdd(&nz, 1);
    __syncthreads();
    if (threadIdx.x == 0) g_is64 = (nz == 0) ? 1 : 0;
}

// ---------------- CSR build ----------------
__global__ void k_zero_counts() {
    int i = blockIdx.x * blockDim.x + threadIdx.x;
    if (i < NN) g_counts[i] = 0;
}

__global__ void k_hist(const int* __restrict__ ei) {
    int e = blockIdx.x * blockDim.x + threadIdx.x;
    if (e < NE) {
        int is64 = g_is64;
        unsigned d = (unsigned)edge_at(ei, (long long)NE + e, is64);
        if (d < NN) atomicAdd(&g_counts[d], 1);
    }
}

__global__ void k_scan1() {
    __shared__ int s[1024];
    int idx = blockIdx.x * 1024 + threadIdx.x;
    int v = (idx < NN) ? g_counts[idx] : 0;
    s[threadIdx.x] = v;
    __syncthreads();
    for (int off = 1; off < 1024; off <<= 1) {
        int t = 0;
        if (threadIdx.x >= off) t = s[threadIdx.x - off];
        __syncthreads();
        s[threadIdx.x] += t;
        __syncthreads();
    }
    if (idx < NN) g_scanTmp[idx] = s[threadIdx.x];
    if (threadIdx.x == 1023) g_partials[blockIdx.x] = s[1023];
}

__global__ void k_scan2(int nblocks) {
    __shared__ int s[128];
    int t = threadIdx.x;
    int v = (t < nblocks) ? g_partials[t] : 0;
    s[t] = v;
    __syncthreads();
    for (int off = 1; off < 128; off <<= 1) {
        int tv = 0;
        if (t >= off) tv = s[t - off];
        __syncthreads();
        s[t] += tv;
        __syncthreads();
    }
    g_partials[t] = s[t];
    if (t == 0) g_rowptr[0] = 0;
}

__global__ void k_scan3() {
    int idx = blockIdx.x * 1024 + threadIdx.x;
    if (idx < NN) {
        int off = (blockIdx.x > 0) ? g_partials[blockIdx.x - 1] : 0;
        int incl = g_scanTmp[idx] + off;
        int excl = incl - g_counts[idx];
        g_rowptr[idx] = excl;
        g_cursor[idx] = excl;
        if (idx == NN - 1) g_rowptr[NN] = incl;
    }
}

__global__ void k_scatter(const int* __restrict__ ei) {
    int e = blockIdx.x * blockDim.x + threadIdx.x;
    if (e < NE) {
        int is64 = g_is64;
        int s = edge_at(ei, e, is64);
        unsigned d = (unsigned)edge_at(ei, (long long)NE + e, is64);
        if (d < NN) {
            int pos = atomicAdd(&g_cursor[d], 1);
            g_srcSorted[pos] = s;
        }
    }
}

// ---------------- packed fp32 -> (hi, lo) bf16x2 split ----------------
__device__ __forceinline__ void split2(float v0, float v1, uint32_t& h, uint32_t& l) {
    asm("cvt.rn.bf16x2.f32 %0, %1, %2;" : "=r"(h) : "f"(v1), "f"(v0));
    float h0 = __uint_as_float(h << 16);
    float h1 = __uint_as_float(h & 0xFFFF0000u);
    float l0 = v0 - h0, l1 = v1 - h1;
    asm("cvt.rn.bf16x2.f32 %0, %1, %2;" : "=r"(l) : "f"(l1), "f"(l0));
}

// ---------------- aggregation: warp per node, writes SPLIT planes ----------------
__global__ void k_agg64(const float* __restrict__ x, const float* __restrict__ epsp) {
    if (blockIdx.x == 0 && threadIdx.x < 128) {
        g_Ssum[threadIdx.x] = 0.f; g_Ssq[threadIdx.x] = 0.f;
    }
    int warp = (blockIdx.x * blockDim.x + threadIdx.x) >> 5;
    int lane = threadIdx.x & 31;
    if (warp >= NN) return;
    int lo = g_rowptr[warp], hi = g_rowptr[warp + 1];
    float eps1 = 1.0f + *epsp;
    const float2* xb = (const float2*)x;
    float2 self = xb[(size_t)warp * 32 + lane];
    float2 acc;
    acc.x = self.x * eps1; acc.y = self.y * eps1;
    for (int e = lo; e < hi; ++e) {
        int s = g_srcSorted[e];
        if ((unsigned)s < NN) {
            float2 v = xb[(size_t)s * 32 + lane];
            acc.x += v.x; acc.y += v.y;
        }
    }
    uint32_t h, l;
    split2(acc.x, acc.y, h, l);
    ((uint32_t*)g_bufAhi)[(size_t)warp * 32 + lane] = h;   // K=64: 32 words/row
    ((uint32_t*)g_bufAlo)[(size_t)warp * 32 + lane] = l;
}

__global__ void k_agg128(const float* __restrict__ epsp) {
    if (blockIdx.x == 0 && threadIdx.x < 128) {
        g_Ssum[threadIdx.x] = 0.f; g_Ssq[threadIdx.x] = 0.f;
    }
    int warp = (blockIdx.x * blockDim.x + threadIdx.x) >> 5;
    int lane = threadIdx.x & 31;
    if (warp >= NN) return;
    int lo = g_rowptr[warp], hi = g_rowptr[warp + 1];
    float eps1 = 1.0f + *epsp;
    const float4* xb = g_bufC;
    float4 self = xb[(size_t)warp * 32 + lane];
    float4 acc;
    acc.x = self.x * eps1; acc.y = self.y * eps1;
    acc.z = self.z * eps1; acc.w = self.w * eps1;
    for (int e = lo; e < hi; ++e) {
        int s = g_srcSorted[e];
        if ((unsigned)s < NN) {
            float4 v = xb[(size_t)s * 32 + lane];
            acc.x += v.x; acc.y += v.y; acc.z += v.z; acc.w += v.w;
        }
    }
    uint32_t h01, l01, h23, l23;
    split2(acc.x, acc.y, h01, l01);
    split2(acc.z, acc.w, h23, l23);
    ((uint2*)g_bufAhi)[(size_t)warp * 32 + lane] = make_uint2(h01, h23);  // 32 uint2/row
    ((uint2*)g_bufAlo)[(size_t)warp * 32 + lane] = make_uint2(l01, l23);
}

// ---------------- weight pre-split into fragment layout ----------------
__device__ __forceinline__ uint32_t pack_bf2(float a, float b) {
    uint32_t r;
    asm("cvt.rn.bf16x2.f32 %0, %1, %2;" : "=r"(r) : "f"(b), "f"(a));
    return r;
}

// slots: 0=wa0(K=64), 1..5 K=128, 6=hwa. W is [K][128] row-major fp32.
__global__ void k_prepAll(const float* __restrict__ w0, const float* __restrict__ w1,
                          const float* __restrict__ w2, const float* __restrict__ w3,
                          const float* __restrict__ w4, const float* __restrict__ w5,
                          const float* __restrict__ w6) {
    int slot = blockIdx.y;
    const float* W;
    int K;
    switch (slot) {
        case 0: W = w0; K = 64; break;
        case 1: W = w1; K = 128; break;
        case 2: W = w2; K = 128; break;
        case 3: W = w3; K = 128; break;
        case 4: W = w4; K = 128; break;
        case 5: W = w5; K = 128; break;
        default: W = w6; K = 128; break;
    }
    int idx = blockIdx.x * 256 + threadIdx.x;
    int NC = K / 16;
    if (idx >= NC * 512) return;
    int lane = idx & 31;
    int t = (idx >> 5) & 15;
    int c = idx >> 9;
    int qr = lane >> 2, qc = lane & 3;
    int nr = t * 8 + qr;
    int k0 = c * 16 + qc * 2;

    float v00 = W[(k0 + 0) * 128 + nr], v01 = W[(k0 + 1) * 128 + nr];
    float v10 = W[(k0 + 8) * 128 + nr], v11 = W[(k0 + 9) * 128 + nr];
    float h00 = __bfloat162float(__float2bfloat16(v00));
    float h01 = __bfloat162float(__float2bfloat16(v01));
    float h10 = __bfloat162float(__float2bfloat16(v10));
    float h11 = __bfloat162float(__float2bfloat16(v11));
    uint4 r;
    r.x = pack_bf2(v00, v01);
    r.y = pack_bf2(v10, v11);
    r.z = pack_bf2(v00 - h00, v01 - h01);
    r.w = pack_bf2(v10 - h10, v11 - h11);
    g_Wfrag[(size_t)slot * 4096 + idx] = r;
}

// ---------------- MMA / LDSM primitives ----------------
__device__ __forceinline__ void mma_bf16(float* d, const uint32_t* a, const uint32_t* b) {
    asm volatile(
        "mma.sync.aligned.m16n8k16.row.col.f32.bf16.bf16.f32 "
        "{%0,%1,%2,%3}, {%4,%5,%6,%7}, {%8,%9}, {%0,%1,%2,%3};\n"
        : "+f"(d[0]), "+f"(d[1]), "+f"(d[2]), "+f"(d[3])
        : "r"(a[0]), "r"(a[1]), "r"(a[2]), "r"(a[3]), "r"(b[0]), "r"(b[1]));
}

__device__ __forceinline__ void ldsm4(uint32_t* r, uint32_t saddr) {
    asm volatile(
        "ldmatrix.sync.aligned.m8n8.x4.shared.b16 {%0,%1,%2,%3}, [%4];"
        : "=r"(r[0]), "=r"(r[1]), "=r"(r[2]), "=r"(r[3]) : "r"(saddr));
}

// =====================================================================
// split-bf16 GEMM — R12 single-buffer schedule, A-frags via ldmatrix.
// smem pitch 24 bf16 (48B): LDSM phase pattern conflict-free (stride 48 mod 128).
// SRC: 0 = pre-split planes (copy staging), 1 = g_bufB fp32 (+BN), 2 = g_bufC fp32
// =====================================================================
#define APITCH 24

template<int K, int SRC, int DST, int SLOT, bool IN_BN, bool OUT_RELU, bool STATS, bool HEAD>
__global__ void __launch_bounds__(256)
k_gemm_mma(const float* __restrict__ bias, const float* __restrict__ gamma,
           const float* __restrict__ beta, const float* __restrict__ hwb,
           const float* __restrict__ hbb, float* __restrict__ outp) {
    const uint4* pW = g_Wfrag + (size_t)SLOT * 4096;

    __shared__ __align__(16) __nv_bfloat16 sAhi[128 * APITCH];
    __shared__ __align__(16) __nv_bfloat16 sAlo[128 * APITCH];
    __shared__ float sSum[128], sSq[128];
    __shared__ float sScale[128], sShift[128];
    __shared__ float sOut[256];              // HEAD epilogue only

    const int tid = threadIdx.x;
    const int lane = tid & 31;
    const int warp = tid >> 5;
    const int wm = warp & 3;
    const int wn = warp >> 2;
    const int qr = lane >> 2;
    const int qc = lane & 3;
    const int rowBase = blockIdx.x * 128;

    const uint32_t baseHi = (uint32_t)__cvta_generic_to_shared(sAhi);
    const uint32_t baseLo = (uint32_t)__cvta_generic_to_shared(sAlo);
    // ldmatrix per-lane byte offset within a 16-row tile starting at row r0:
    //   (r0 + (lane&15))*48 + (lane>>4)*16
    const uint32_t lmOff = (uint32_t)(lane & 15) * (APITCH * 2) + (uint32_t)(lane >> 4) * 16;

    if (STATS && tid < 128) { sSum[tid] = 0.f; sSq[tid] = 0.f; }
    if (HEAD) sOut[tid] = 0.f;
    if (IN_BN) {
        if (tid < 128) {
            float mu = g_Ssum[tid] * (1.0f / NN);
            float var = fmaxf(g_Ssq[tid] * (1.0f / NN) - mu * mu, 0.f);
            float sc = gamma[tid] * rsqrtf(var + 1e-5f);
            sScale[tid] = sc;
            sShift[tid] = beta[tid] - mu * sc;
        }
        __syncthreads();
    }

    float acc[2][8][4];
#pragma unroll
    for (int m = 0; m < 2; m++)
#pragma unroll
        for (int n = 0; n < 8; n++)
#pragma unroll
            for (int j = 0; j < 4; j++) acc[m][n][j] = 0.f;

    for (int kk = 0; kk < K; kk += 16) {
        // ---- stage A tile 128x16 into pitch-24 smem ----
        if (SRC == 0) {
            int row = tid >> 1, half = tid & 1;
            int gr = rowBase + row;
            uint4 h = make_uint4(0, 0, 0, 0), l = make_uint4(0, 0, 0, 0);
            if (gr < NN) {
                size_t off = (size_t)gr * K + kk + half * 8;
                h = *(const uint4*)((const __nv_bfloat16*)g_bufAhi + off);
                l = *(const uint4*)((const __nv_bfloat16*)g_bufAlo + off);
            }
            *(uint4*)(sAhi + row * APITCH + half * 8) = h;
            *(uint4*)(sAlo + row * APITCH + half * 8) = l;
        } else {
            const float* A = (SRC == 1) ? (const float*)g_bufB : (const float*)g_bufC;
#pragma unroll
            for (int it = 0; it < 2; it++) {
                int f = it * 256 + tid;
                int row = f >> 2;
                int c4 = (f & 3) << 2;
                int gr = rowBase + row;
                float4 v = make_float4(0.f, 0.f, 0.f, 0.f);
                if (gr < NN) v = *(const float4*)(A + (size_t)gr * K + kk + c4);
                if (IN_BN) {
                    int kb = kk + c4;
                    v.x = fmaxf(v.x * sScale[kb + 0] + sShift[kb + 0], 0.f);
                    v.y = fmaxf(v.y * sScale[kb + 1] + sShift[kb + 1], 0.f);
                    v.z = fmaxf(v.z * sScale[kb + 2] + sShift[kb + 2], 0.f);
                    v.w = fmaxf(v.w * sScale[kb + 3] + sShift[kb + 3], 0.f);
                }
                uint32_t h01, l01, h23, l23;
                split2(v.x, v.y, h01, l01);
                split2(v.z, v.w, h23, l23);
                *(uint2*)(sAhi + row * APITCH + c4) = make_uint2(h01, h23);
                *(uint2*)(sAlo + row * APITCH + c4) = make_uint2(l01, l23);
            }
        }
        __syncthreads();

        int c = kk / 16;
        uint4 bf[8];
#pragma unroll
        for (int n = 0; n < 8; n++)
            bf[n] = pW[(size_t)((c * 16 + wn * 8 + n) * 32 + lane)];

#pragma unroll
        for (int m = 0; m < 2; m++) {
            uint32_t r0bytes = (uint32_t)(wm * 32 + m * 16) * (APITCH * 2);
            uint32_t ah[4], al[4];
            ldsm4(ah, baseHi + r0bytes + lmOff);
            ldsm4(al, baseLo + r0bytes + lmOff);
#pragma unroll
            for (int n = 0; n < 8; n++) {
                uint32_t bh[2] = {bf[n].x, bf[n].y};
                uint32_t bl[2] = {bf[n].z, bf[n].w};
                mma_bf16(acc[m][n], ah, bh);
                mma_bf16(acc[m][n], ah, bl);
                mma_bf16(acc[m][n], al, bh);
            }
        }
        __syncthreads();
    }

    // ---- epilogue ----
    if (HEAD) {
#pragma unroll
        for (int m = 0; m < 2; m++) {
            int rl = wm * 32 + m * 16 + qr;
#pragma unroll
            for (int n = 0; n < 8; n++) {
                int cc = wn * 64 + n * 8 + qc * 2;
                float b0 = bias[cc], b1 = bias[cc + 1];
                float v0 = fmaxf(acc[m][n][0] + b0, 0.f), v1 = fmaxf(acc[m][n][1] + b1, 0.f);
                float v2 = fmaxf(acc[m][n][2] + b0, 0.f), v3 = fmaxf(acc[m][n][3] + b1, 0.f);
                float w00 = hwb[cc * 2 + 0], w01 = hwb[cc * 2 + 1];
                float w10 = hwb[(cc + 1) * 2 + 0], w11 = hwb[(cc + 1) * 2 + 1];
                if (rowBase + rl < NN) {
                    atomicAdd(&sOut[rl * 2 + 0], v0 * w00 + v1 * w10);
                    atomicAdd(&sOut[rl * 2 + 1], v0 * w01 + v1 * w11);
                }
                if (rowBase + rl + 8 < NN) {
                    atomicAdd(&sOut[(rl + 8) * 2 + 0], v2 * w00 + v3 * w10);
                    atomicAdd(&sOut[(rl + 8) * 2 + 1], v2 * w01 + v3 * w11);
                }
            }
        }
        __syncthreads();
        if (tid < 128) {
            int r = rowBase + tid;
            if (r < NN) {
                outp[(size_t)r * 2 + 0] = sOut[tid * 2 + 0] + hbb[0];
                outp[(size_t)r * 2 + 1] = sOut[tid * 2 + 1] + hbb[1];
            }
        }
        return;
    }

    float* out = (DST == 1) ? (float*)g_bufB : (float*)g_bufC;
    float cS[16], cQ[16];
    if (STATS) {
#pragma unroll
        for (int j = 0; j < 16; j++) { cS[j] = 0.f; cQ[j] = 0.f; }
    }

#pragma unroll
    for (int m = 0; m < 2; m++) {
        int r = rowBase + wm * 32 + m * 16 + qr;
#pragma unroll
        for (int n = 0; n < 8; n++) {
            int cc = wn * 64 + n * 8 + qc * 2;
            float b0 = bias[cc], b1 = bias[cc + 1];
            float v0 = acc[m][n][0] + b0, v1 = acc[m][n][1] + b1;
            float v2 = acc[m][n][2] + b0, v3 = acc[m][n][3] + b1;
            if (OUT_RELU) {
                v0 = fmaxf(v0, 0.f); v1 = fmaxf(v1, 0.f);
                v2 = fmaxf(v2, 0.f); v3 = fmaxf(v3, 0.f);
            }
            if (r < NN) {
                *(float2*)(out + (size_t)r * 128 + cc) = make_float2(v0, v1);
                if (STATS) {
                    cS[n * 2] += v0; cS[n * 2 + 1] += v1;
                    cQ[n * 2] += v0 * v0; cQ[n * 2 + 1] += v1 * v1;
                }
            }
            if (r + 8 < NN) {
                *(float2*)(out + (size_t)(r + 8) * 128 + cc) = make_float2(v2, v3);
                if (STATS) {
                    cS[n * 2] += v2; cS[n * 2 + 1] += v3;
                    cQ[n * 2] += v2 * v2; cQ[n * 2 + 1] += v3 * v3;
                }
            }
        }
    }

    if (STATS) {
#pragma unroll
        for (int n = 0; n < 8; n++) {
            int cc = wn * 64 + n * 8 + qc * 2;
            atomicAdd(&sSum[cc], cS[n * 2]);
            atomicAdd(&sSum[cc + 1], cS[n * 2 + 1]);
            atomicAdd(&sSq[cc], cQ[n * 2]);
            atomicAdd(&sSq[cc + 1], cQ[n * 2 + 1]);
        }
        __syncthreads();
        if (tid < 128) {
            atomicAdd(&g_Ssum[tid], sSum[tid]);
            atomicAdd(&g_Ssq[tid], sSq[tid]);
        }
    }
}

// ---------------- launch ----------------
extern "C" void kernel_launch(void* const* d_in, const int* in_sizes, int n_in,
                              void* d_out, int out_size) {
    const float* x = (const float*)d_in[0];
    const int* ei = (const int*)d_in[1];

    const float* wa[3]; const float* ba[3]; const float* gm[3]; const float* be[3];
    const float* wb[3]; const float* bb[3]; const float* ep[3];
    for (int l = 0; l < 3; l++) {
        int b = 2 + 7 * l;
        wa[l] = (const float*)d_in[b + 0];
        ba[l] = (const float*)d_in[b + 1];
        gm[l] = (const float*)d_in[b + 2];
        be[l] = (const float*)d_in[b + 3];
        wb[l] = (const float*)d_in[b + 4];
        bb[l] = (const float*)d_in[b + 5];
        ep[l] = (const float*)d_in[b + 6];
    }
    const float* hwa = (const float*)d_in[23];
    const float* hba = (const float*)d_in[24];
    const float* hwb = (const float*)d_in[25];
    const float* hbb = (const float*)d_in[26];
    float* out = (float*)d_out;

    const int NB1 = (NN + 1023) / 1024;       // 98
    const int GB = (NN + 127) / 128;           // 782
    const int AGGB = (NN + 7) / 8;             // 12500

    // one-shot weight pre-split (K=128 slots need 4096 threads -> 16 blocks)
    dim3 pg(16, 7);
    k_prepAll<<<pg, 256>>>(wa[0], wb[0], wa[1], wb[1], wa[2], wb[2], hwa);

    // edge dtype detection + CSR build
    k_detect<<<1, 256>>>(ei);
    k_zero_counts<<<(NN + 255) / 256, 256>>>();
    k_hist<<<(NE + 255) / 256, 256>>>(ei);
    k_scan1<<<NB1, 1024>>>();
    k_scan2<<<1, 128>>>(NB1);
    k_scan3<<<NB1, 1024>>>();
    k_scatter<<<(NE + 255) / 256, 256>>>(ei);

    // ---- layer 0 (din = 64): x -> Ahi/Alo -> bufB -> bufC ----
    k_agg64<<<AGGB, 256>>>(x, ep[0]);
    k_gemm_mma<64, 0, 1, 0, false, false, true, false><<<GB, 256>>>(
        ba[0], nullptr, nullptr, nullptr, nullptr, nullptr);
    k_gemm_mma<128, 1, 2, 1, true, true, false, false><<<GB, 256>>>(
        bb[0], gm[0], be[0], nullptr, nullptr, nullptr);

    // ---- layer 1 ----
    k_agg128<<<AGGB, 256>>>(ep[1]);
    k_gemm_mma<128, 0, 1, 2, false, false, true, false><<<GB, 256>>>(
        ba[1], nullptr, nullptr, nullptr, nullptr, nullptr);
    k_gemm_mma<128, 1, 2, 3, true, true, false, false><<<GB, 256>>>(
        bb[1], gm[1], be[1], nullptr, nullptr, nullptr);

    // ---- layer 2 ----
    k_agg128<<<AGGB, 256>>>(ep[2]);
    k_gemm_mma<128, 0, 1, 4, false, false, true, false><<<GB, 256>>>(
        ba[2], nullptr, nullptr, nullptr, nullptr, nullptr);
    k_gemm_mma<128, 1, 2, 5, true, true, false, false><<<GB, 256>>>(
        bb[2], gm[2], be[2], nullptr, nullptr, nullptr);

    // ---- fused head: bufC -> out ----
    k_gemm_mma<128, 2, 2, 6, false, false, false, true><<<GB, 256>>>(
        hba, nullptr, nullptr, hwb, hbb, out);
}